// round 1
// baseline (speedup 1.0000x reference)
#include <cuda_runtime.h>
#include <cstdint>

#define N_NODES 100000
#define HID 64

// Scratch (static device globals: allocation-free per harness rules)
__device__ float g_deg[N_NODES];                // degree, then dinv in-place
__device__ float g_hs [N_NODES * HID];          // dinv-scaled transformed features
__device__ float g_tmp[N_NODES * HID];          // scatter accumulator
__device__ int   g_is32;                        // edge_index dtype flag

// ---------------------------------------------------------------------------
// Detect whether edge_index is int32 or int64. If the buffer holds int32
// values v in [0, N_NODES), reading as int64 gives v0 + (v1<<32) which is
// >= 2^32 unless v1 == 0 (prob 1e-5 per slot). 64 samples -> certainty.
// ---------------------------------------------------------------------------
__global__ void detect_kernel(const void* ei) {
    if (threadIdx.x == 0 && blockIdx.x == 0) {
        const long long* p = (const long long*)ei;
        int bad = 0;
        for (int i = 0; i < 64; i++) {
            long long v = p[i];
            if (v < 0 || v >= N_NODES) bad = 1;
        }
        g_is32 = bad;
    }
}

__global__ void deg_init_kernel(int n) {
    int i = blockIdx.x * blockDim.x + threadIdx.x;
    if (i < n) g_deg[i] = 1.0f;   // self-loop weight
}

__global__ void deg_accum_kernel(const void* ei, const float* __restrict__ w, int E) {
    int e = blockIdx.x * blockDim.x + threadIdx.x;
    if (e >= E) return;
    int dst;
    if (g_is32) dst = ((const int*)ei)[E + e];
    else        dst = (int)((const long long*)ei)[E + e];
    atomicAdd(&g_deg[dst], w[e]);
}

__global__ void dinv_kernel(int n) {
    int i = blockIdx.x * blockDim.x + threadIdx.x;
    if (i < n) g_deg[i] = rsqrtf(g_deg[i]);   // deg >= 1 always (self-loop)
}

// ---------------------------------------------------------------------------
// Layer-1 GEMM: hs[row] = dinv[row] * (x[row] @ W1); tmp[row] = hs[row]
// One thread per row, 64 accumulators, W1 staged in smem (broadcast LDS.128).
// ---------------------------------------------------------------------------
__global__ __launch_bounds__(256) void gemm1_kernel(
    const float* __restrict__ x, const float* __restrict__ W, int n)
{
    __shared__ float sW[HID * HID];
    for (int i = threadIdx.x; i < HID * HID; i += blockDim.x) sW[i] = W[i];
    __syncthreads();

    int row = blockIdx.x * blockDim.x + threadIdx.x;
    if (row >= n) return;

    float acc[HID];
    #pragma unroll
    for (int j = 0; j < HID; j++) acc[j] = 0.0f;

    const float4* xr = (const float4*)(x + (size_t)row * HID);
    for (int k4 = 0; k4 < HID / 4; k4++) {
        float4 xv = __ldg(&xr[k4]);
        float xs[4] = {xv.x, xv.y, xv.z, xv.w};
        #pragma unroll
        for (int s = 0; s < 4; s++) {
            int k = k4 * 4 + s;
            float xk = xs[s];
            #pragma unroll
            for (int j4 = 0; j4 < HID / 4; j4++) {
                float4 wv = *(const float4*)&sW[k * HID + j4 * 4];
                acc[j4 * 4 + 0] += xk * wv.x;
                acc[j4 * 4 + 1] += xk * wv.y;
                acc[j4 * 4 + 2] += xk * wv.z;
                acc[j4 * 4 + 3] += xk * wv.w;
            }
        }
    }

    float di = g_deg[row];  // dinv
    float4* ph = (float4*)&g_hs [(size_t)row * HID];
    float4* pt = (float4*)&g_tmp[(size_t)row * HID];
    #pragma unroll
    for (int j4 = 0; j4 < HID / 4; j4++) {
        float4 v = make_float4(di * acc[j4 * 4 + 0], di * acc[j4 * 4 + 1],
                               di * acc[j4 * 4 + 2], di * acc[j4 * 4 + 3]);
        ph[j4] = v;
        pt[j4] = v;   // self-loop contribution initializes the accumulator
    }
}

// ---------------------------------------------------------------------------
// Layer-2 GEMM: act = relu(dinv*tmp + b1); hs = dinv*(act @ W2); tmp = hs
// (tmp row fully read before overwritten by the same thread -> safe reuse)
// ---------------------------------------------------------------------------
__global__ __launch_bounds__(256) void gemm2_kernel(
    const float* __restrict__ W, const float* __restrict__ b1, int n)
{
    __shared__ float sW[HID * HID];
    __shared__ float sB[HID];
    for (int i = threadIdx.x; i < HID * HID; i += blockDim.x) sW[i] = W[i];
    if (threadIdx.x < HID) sB[threadIdx.x] = b1[threadIdx.x];
    __syncthreads();

    int row = blockIdx.x * blockDim.x + threadIdx.x;
    if (row >= n) return;

    float di = g_deg[row];
    float acc[HID];
    #pragma unroll
    for (int j = 0; j < HID; j++) acc[j] = 0.0f;

    const float4* tr = (const float4*)&g_tmp[(size_t)row * HID];
    for (int k4 = 0; k4 < HID / 4; k4++) {
        float4 tv = tr[k4];
        float xs[4] = {fmaxf(di * tv.x + sB[k4 * 4 + 0], 0.0f),
                       fmaxf(di * tv.y + sB[k4 * 4 + 1], 0.0f),
                       fmaxf(di * tv.z + sB[k4 * 4 + 2], 0.0f),
                       fmaxf(di * tv.w + sB[k4 * 4 + 3], 0.0f)};
        #pragma unroll
        for (int s = 0; s < 4; s++) {
            int k = k4 * 4 + s;
            float xk = xs[s];
            #pragma unroll
            for (int j4 = 0; j4 < HID / 4; j4++) {
                float4 wv = *(const float4*)&sW[k * HID + j4 * 4];
                acc[j4 * 4 + 0] += xk * wv.x;
                acc[j4 * 4 + 1] += xk * wv.y;
                acc[j4 * 4 + 2] += xk * wv.z;
                acc[j4 * 4 + 3] += xk * wv.w;
            }
        }
    }

    float4* ph = (float4*)&g_hs [(size_t)row * HID];
    float4* pt = (float4*)&g_tmp[(size_t)row * HID];
    #pragma unroll
    for (int j4 = 0; j4 < HID / 4; j4++) {
        float4 v = make_float4(di * acc[j4 * 4 + 0], di * acc[j4 * 4 + 1],
                               di * acc[j4 * 4 + 2], di * acc[j4 * 4 + 3]);
        ph[j4] = v;
        pt[j4] = v;
    }
}

// ---------------------------------------------------------------------------
// Edge scatter: tmp[dst] += w_e * hs[src]. 16 threads per edge, each owning
// one float4 lane; vectorized red.global.add.v4.f32 (L2-resident targets).
// ---------------------------------------------------------------------------
__global__ __launch_bounds__(256) void scatter_kernel(
    const void* ei, const float* __restrict__ w, int E)
{
    int idx = blockIdx.x * blockDim.x + threadIdx.x;
    int e = idx >> 4;
    if (e >= E) return;
    int c = (threadIdx.x & 15) * 4;

    int src, dst;
    if (g_is32) {
        const int* p = (const int*)ei;
        src = p[e]; dst = p[E + e];
    } else {
        const long long* p = (const long long*)ei;
        src = (int)p[e]; dst = (int)p[E + e];
    }
    float we = w[e];

    float4 hv = *(const float4*)(g_hs + (size_t)src * HID + c);
    float* q = g_tmp + (size_t)dst * HID + c;
    asm volatile(
        "red.global.add.v4.f32 [%0], {%1, %2, %3, %4};"
        :: "l"(q), "f"(we * hv.x), "f"(we * hv.y), "f"(we * hv.z), "f"(we * hv.w)
        : "memory");
}

// ---------------------------------------------------------------------------
// Final epilogue: out = dinv * tmp + b2
// ---------------------------------------------------------------------------
__global__ __launch_bounds__(256) void final_kernel(
    const float* __restrict__ b2, float* __restrict__ out, int n)
{
    int idx = blockIdx.x * blockDim.x + threadIdx.x;
    if (idx >= n * (HID / 4)) return;
    int row = idx >> 4;
    int c = (idx & 15) * 4;
    float di = g_deg[row];
    float4 v  = *(const float4*)&g_tmp[(size_t)row * HID + c];
    float4 bb = *(const float4*)&b2[c];
    float4 o = make_float4(di * v.x + bb.x, di * v.y + bb.y,
                           di * v.z + bb.z, di * v.w + bb.w);
    *(float4*)(out + (size_t)row * HID + c) = o;
}

extern "C" void kernel_launch(void* const* d_in, const int* in_sizes, int n_in,
                              void* d_out, int out_size)
{
    const float* x  = (const float*)d_in[0];
    const void*  ei = d_in[1];               // int32 or int64, detected on device
    const float* ew = (const float*)d_in[2];
    const float* W1 = (const float*)d_in[3];
    const float* b1 = (const float*)d_in[4];
    const float* W2 = (const float*)d_in[5];
    const float* b2 = (const float*)d_in[6];
    float* out = (float*)d_out;

    int n = in_sizes[0] / HID;
    int E = in_sizes[2];

    const int T = 256;
    int gN  = (n + T - 1) / T;
    int gE  = (E + T - 1) / T;
    int gE16 = (E * 16 + T - 1) / T;   // 19.2M items, fits int
    int gN16 = (n * 16 + T - 1) / T;

    detect_kernel<<<1, 32>>>(ei);
    deg_init_kernel<<<gN, T>>>(n);
    deg_accum_kernel<<<gE, T>>>(ei, ew, E);
    dinv_kernel<<<gN, T>>>(n);

    // Layer 1
    gemm1_kernel<<<gN, T>>>(x, W1, n);
    scatter_kernel<<<gE16, T>>>(ei, ew, E);

    // Layer 2 (fuses: dinv*tmp + b1, relu, GEMM, dinv scale, self-loop init)
    gemm2_kernel<<<gN, T>>>(W2, b1, n);
    scatter_kernel<<<gE16, T>>>(ei, ew, E);

    final_kernel<<<gN16, T>>>(b2, out, n);
}

// round 4
// speedup vs baseline: 1.1763x; 1.1763x over previous
#include <cuda_runtime.h>
#include <cstdint>

#define N_NODES 100000
#define E_MAX   1200000
#define HID 64

// ---- static device scratch (allocation-free) ----
__device__ float g_deg [N_NODES];            // weighted degree (incl. self-loop)
__device__ float g_hs  [N_NODES * HID];      // dinv-scaled transformed features
__device__ float g_act [N_NODES * HID];      // layer-1 activations
__device__ int   g_cnt [N_NODES];            // in-degree count
__device__ int   g_offs[N_NODES];            // CSR exclusive offsets
__device__ int   g_cur [N_NODES];            // binning cursors
__device__ int   g_bsum[512];                // block sums for scan
__device__ int   g_boff[512];                // scanned block offsets
__device__ int   g_csrc[E_MAX];              // CSR: src per edge (grouped by dst)
__device__ float g_csrw[E_MAX];              // CSR: weight per edge
__device__ int   g_is32;                     // edge_index dtype flag

// ---------------------------------------------------------------------------
// init: zero counts, deg = 1 (self-loop), detect edge_index dtype.
// ---------------------------------------------------------------------------
__global__ void init_kernel(const void* ei, int n) {
    int i = blockIdx.x * blockDim.x + threadIdx.x;
    if (i < n) { g_deg[i] = 1.0f; g_cnt[i] = 0; }
    if (i == 0) {
        const long long* p = (const long long*)ei;
        int bad = 0;
        for (int k = 0; k < 64; k++) {
            long long v = p[k];
            if (v < 0 || v >= N_NODES) bad = 1;
        }
        g_is32 = bad;
    }
}

__device__ __forceinline__ void decode_edge(const void* ei, int E, int e,
                                            int& src, int& dst) {
    if (g_is32) {
        const int* p = (const int*)ei;
        src = p[e]; dst = p[E + e];
    } else {
        const long long* p = (const long long*)ei;
        src = (int)p[e]; dst = (int)p[E + e];
    }
}

// histogram: count[dst]++ and deg[dst] += w  (spread int/float atomics)
__global__ void hist_kernel(const void* ei, const float* __restrict__ w, int E) {
    int e = blockIdx.x * blockDim.x + threadIdx.x;
    if (e >= E) return;
    int src, dst;
    decode_edge(ei, E, e, src, dst);
    atomicAdd(&g_cnt[dst], 1);
    atomicAdd(&g_deg[dst], w[e]);
}

// ---- 3-kernel exclusive scan of g_cnt -> g_offs ----
__global__ void scan1_kernel(int n) {
    __shared__ int s[256];
    int t = threadIdx.x;
    int i = blockIdx.x * 256 + t;
    int v = (i < n) ? g_cnt[i] : 0;
    s[t] = v; __syncthreads();
    #pragma unroll
    for (int d = 1; d < 256; d <<= 1) {
        int x = (t >= d) ? s[t - d] : 0;
        __syncthreads();
        s[t] += x; __syncthreads();
    }
    if (i < n) g_offs[i] = s[t] - v;            // exclusive within block
    if (t == 255) g_bsum[blockIdx.x] = s[255];  // block total
}

__global__ void scan2_kernel(int nblocks) {
    __shared__ int s[512];
    int t = threadIdx.x;
    int v = (t < nblocks) ? g_bsum[t] : 0;
    s[t] = v; __syncthreads();
    #pragma unroll
    for (int d = 1; d < 512; d <<= 1) {
        int x = (t >= d) ? s[t - d] : 0;
        __syncthreads();
        s[t] += x; __syncthreads();
    }
    if (t < nblocks) g_boff[t] = s[t] - v;      // exclusive block offsets
}

__global__ void scan3_kernel(int n) {
    int i = blockIdx.x * blockDim.x + threadIdx.x;
    if (i >= n) return;
    int o = g_offs[i] + g_boff[i >> 8];
    g_offs[i] = o;
    g_cur[i]  = o;                              // binning cursor copy
}

// bin edges into CSR grouped by dst
__global__ void bin_kernel(const void* ei, const float* __restrict__ w, int E) {
    int e = blockIdx.x * blockDim.x + threadIdx.x;
    if (e >= E) return;
    int src, dst;
    decode_edge(ei, E, e, src, dst);
    int pos = atomicAdd(&g_cur[dst], 1);
    g_csrc[pos] = src;
    g_csrw[pos] = w[e];
}

// ---------------------------------------------------------------------------
// GEMM: hs[row] = rsqrt(deg[row]) * (in[row] @ W). One thread per row,
// W staged in smem. SRC=0: read from xp (harness input); SRC=1: read g_act
// (device symbol referenced INSIDE device code only).
// ---------------------------------------------------------------------------
template <int SRC>
__global__ __launch_bounds__(256) void gemm_kernel(
    const float* __restrict__ xp, const float* __restrict__ W, int n)
{
    __shared__ float sW[HID * HID];
    for (int i = threadIdx.x; i < HID * HID; i += blockDim.x) sW[i] = W[i];
    __syncthreads();

    int row = blockIdx.x * blockDim.x + threadIdx.x;
    if (row >= n) return;

    const float* in = (SRC == 0) ? xp : (const float*)g_act;

    float acc[HID];
    #pragma unroll
    for (int j = 0; j < HID; j++) acc[j] = 0.0f;

    const float4* xr = (const float4*)(in + (size_t)row * HID);
    #pragma unroll
    for (int k4 = 0; k4 < HID / 4; k4++) {
        float4 xv = __ldg(&xr[k4]);
        float xs[4] = {xv.x, xv.y, xv.z, xv.w};
        #pragma unroll
        for (int s = 0; s < 4; s++) {
            int k = k4 * 4 + s;
            float xk = xs[s];
            #pragma unroll
            for (int j4 = 0; j4 < HID / 4; j4++) {
                float4 wv = *(const float4*)&sW[k * HID + j4 * 4];
                acc[j4 * 4 + 0] += xk * wv.x;
                acc[j4 * 4 + 1] += xk * wv.y;
                acc[j4 * 4 + 2] += xk * wv.z;
                acc[j4 * 4 + 3] += xk * wv.w;
            }
        }
    }

    float di = rsqrtf(g_deg[row]);
    float4* ph = (float4*)&g_hs[(size_t)row * HID];
    #pragma unroll
    for (int j4 = 0; j4 < HID / 4; j4++) {
        ph[j4] = make_float4(di * acc[j4 * 4 + 0], di * acc[j4 * 4 + 1],
                             di * acc[j4 * 4 + 2], di * acc[j4 * 4 + 3]);
    }
}

// ---------------------------------------------------------------------------
// Aggregation: one warp per destination node. Lane l owns features [2l, 2l+1].
// acc = hs[dst] (self-loop) + sum_e w_e * hs[src_e]; epilogue by MODE:
//   MODE 0: g_act[dst] = relu(dinv*acc + bias)
//   MODE 1: outp [dst] = dinv*acc + bias
// ---------------------------------------------------------------------------
template <int MODE>
__global__ __launch_bounds__(256) void agg_kernel(
    const float* __restrict__ bias, float* __restrict__ outp, int n)
{
    int gtid = blockIdx.x * blockDim.x + threadIdx.x;
    int dst  = gtid >> 5;
    if (dst >= n) return;
    int lane = threadIdx.x & 31;

    int beg = g_offs[dst];
    int cnt = g_cnt[dst];

    float2 acc = *(const float2*)&g_hs[(size_t)dst * HID + lane * 2];  // self-loop

    for (int base = 0; base < cnt; base += 32) {
        int m = cnt - base; if (m > 32) m = 32;
        int   se = 0; float we = 0.0f;
        if (lane < m) {
            se = g_csrc[beg + base + lane];
            we = g_csrw[beg + base + lane];
        }
        for (int t = 0; t < m; t++) {
            int   ss = __shfl_sync(0xffffffffu, se, t);
            float ww = __shfl_sync(0xffffffffu, we, t);
            float2 hv = __ldg((const float2*)&g_hs[(size_t)ss * HID + lane * 2]);
            acc.x += ww * hv.x;
            acc.y += ww * hv.y;
        }
    }

    float di = rsqrtf(g_deg[dst]);
    float bx = bias[lane * 2], by = bias[lane * 2 + 1];
    float ox = di * acc.x + bx;
    float oy = di * acc.y + by;
    if (MODE == 0) {
        ox = fmaxf(ox, 0.0f);
        oy = fmaxf(oy, 0.0f);
        *(float2*)&g_act[(size_t)dst * HID + lane * 2] = make_float2(ox, oy);
    } else {
        *(float2*)&outp[(size_t)dst * HID + lane * 2] = make_float2(ox, oy);
    }
}

extern "C" void kernel_launch(void* const* d_in, const int* in_sizes, int n_in,
                              void* d_out, int out_size)
{
    const float* x  = (const float*)d_in[0];
    const void*  ei = d_in[1];               // int32 or int64, device-detected
    const float* ew = (const float*)d_in[2];
    const float* W1 = (const float*)d_in[3];
    const float* b1 = (const float*)d_in[4];
    const float* W2 = (const float*)d_in[5];
    const float* b2 = (const float*)d_in[6];
    float* out = (float*)d_out;

    int n = in_sizes[0] / HID;
    int E = in_sizes[2];

    const int T = 256;
    int gN   = (n + T - 1) / T;              // 391
    int gE   = (E + T - 1) / T;
    int gN32 = (n * 32 + T - 1) / T;         // warp-per-node

    // ---- CSR build (once, used by both layers) ----
    init_kernel <<<gN, T>>>(ei, n);
    hist_kernel <<<gE, T>>>(ei, ew, E);
    scan1_kernel<<<gN, 256>>>(n);
    scan2_kernel<<<1, 512>>>(gN);
    scan3_kernel<<<gN, T>>>(n);
    bin_kernel  <<<gE, T>>>(ei, ew, E);

    // ---- layer 1 ----
    gemm_kernel<0><<<gN, T>>>(x, W1, n);
    agg_kernel<0><<<gN32, T>>>(b1, nullptr, n);

    // ---- layer 2 (input read from g_act inside the kernel) ----
    gemm_kernel<1><<<gN, T>>>(nullptr, W2, n);
    agg_kernel<1><<<gN32, T>>>(b2, out, n);
}

// round 7
// speedup vs baseline: 1.2113x; 1.0298x over previous
#include <cuda_runtime.h>
#include <cstdint>

#define N_NODES 100000
#define E_MAX   1200000
#define HID 64

// ---- static device scratch (allocation-free) ----
__device__ float g_deg [N_NODES];            // sum of incoming edge weights (no self)
__device__ float g_hs  [N_NODES * HID];      // raw transformed features (XW)
__device__ float g_act [N_NODES * HID];      // layer-1 activations
__device__ int   g_cnt [N_NODES];            // in-degree count
__device__ int   g_offs[N_NODES];            // CSR exclusive offsets
__device__ int   g_cur [N_NODES];            // binning cursors
__device__ int   g_bsum[512];                // per-block count sums (scan1 out)
__device__ int2  g_csr [E_MAX];              // CSR entry: {src, bits(w*dinv[src])}
__device__ int   g_is32;                     // edge_index dtype flag

__device__ __forceinline__ void decode_edge(const void* ei, int E, int e,
                                            int& src, int& dst) {
    if (g_is32) {
        const int* p = (const int*)ei;
        src = p[e]; dst = p[E + e];
    } else {
        const long long* p = (const long long*)ei;
        src = (int)p[e]; dst = (int)p[E + e];
    }
}

// ---------------------------------------------------------------------------
// init: zero deg/cnt, detect edge_index dtype.
// ---------------------------------------------------------------------------
__global__ void init_kernel(const void* ei, int n) {
    int i = blockIdx.x * blockDim.x + threadIdx.x;
    if (i < n) { g_deg[i] = 0.0f; g_cnt[i] = 0; }
    if (i == 0) {
        const long long* p = (const long long*)ei;
        int bad = 0;
        for (int k = 0; k < 64; k++) {
            long long v = p[k];
            if (v < 0 || v >= N_NODES) bad = 1;
        }
        g_is32 = bad;
    }
}

// ---------------------------------------------------------------------------
// Fused: blocks [0, gE) run the edge histogram (cnt++/deg+=w atomics);
// blocks [gE, gE+gN) run the layer-1 GEMM rows (hs = x @ W1, unscaled).
// Independent work; the atomic-latency histogram hides under the FFMA GEMM.
// ---------------------------------------------------------------------------
__global__ __launch_bounds__(256) void hist_gemm1_kernel(
    const void* ei, const float* __restrict__ w,
    const float* __restrict__ x, const float* __restrict__ W,
    int n, int E, int gE)
{
    if ((int)blockIdx.x < gE) {
        int e = blockIdx.x * blockDim.x + threadIdx.x;
        if (e >= E) return;
        int src, dst;
        decode_edge(ei, E, e, src, dst);
        atomicAdd(&g_cnt[dst], 1);
        atomicAdd(&g_deg[dst], w[e]);
        return;
    }

    __shared__ float sW[HID * HID];
    for (int i = threadIdx.x; i < HID * HID; i += blockDim.x) sW[i] = W[i];
    __syncthreads();

    int row = (blockIdx.x - gE) * blockDim.x + threadIdx.x;
    if (row >= n) return;

    float acc[HID];
    #pragma unroll
    for (int j = 0; j < HID; j++) acc[j] = 0.0f;

    const float4* xr = (const float4*)(x + (size_t)row * HID);
    #pragma unroll
    for (int k4 = 0; k4 < HID / 4; k4++) {
        float4 xv = __ldg(&xr[k4]);
        float xs[4] = {xv.x, xv.y, xv.z, xv.w};
        #pragma unroll
        for (int s = 0; s < 4; s++) {
            int k = k4 * 4 + s;
            float xk = xs[s];
            #pragma unroll
            for (int j4 = 0; j4 < HID / 4; j4++) {
                float4 wv = *(const float4*)&sW[k * HID + j4 * 4];
                acc[j4 * 4 + 0] += xk * wv.x;
                acc[j4 * 4 + 1] += xk * wv.y;
                acc[j4 * 4 + 2] += xk * wv.z;
                acc[j4 * 4 + 3] += xk * wv.w;
            }
        }
    }

    float4* ph = (float4*)&g_hs[(size_t)row * HID];
    #pragma unroll
    for (int j4 = 0; j4 < HID / 4; j4++) {
        ph[j4] = make_float4(acc[j4 * 4 + 0], acc[j4 * 4 + 1],
                             acc[j4 * 4 + 2], acc[j4 * 4 + 3]);
    }
}

// ---- scan stage 1: per-block exclusive scan of g_cnt, block sums out ----
__global__ void scan1_kernel(int n) {
    __shared__ int s[256];
    int t = threadIdx.x;
    int i = blockIdx.x * 256 + t;
    int v = (i < n) ? g_cnt[i] : 0;
    s[t] = v; __syncthreads();
    #pragma unroll
    for (int d = 1; d < 256; d <<= 1) {
        int x = (t >= d) ? s[t - d] : 0;
        __syncthreads();
        s[t] += x; __syncthreads();
    }
    if (i < n) g_offs[i] = s[t] - v;            // exclusive within block
    if (t == 255) g_bsum[blockIdx.x] = s[255];  // block total
}

// ---- scan stage 2+3 fused: each block redundantly reduces the block sums
//      below its id, then adds the prefix to its offsets ----
__global__ void scan23_kernel(int n, int nblocks) {
    __shared__ int s[256];
    int t = threadIdx.x;
    int bid = blockIdx.x;
    int v = 0;
    for (int b = t; b < nblocks; b += 256)
        if (b < bid) v += g_bsum[b];
    s[t] = v; __syncthreads();
    #pragma unroll
    for (int d = 128; d > 0; d >>= 1) {
        if (t < d) s[t] += s[t + d];
        __syncthreads();
    }
    int prefix = s[0];
    int i = bid * 256 + t;
    if (i < n) {
        int o = g_offs[i] + prefix;
        g_offs[i] = o;
        g_cur[i]  = o;
    }
}

// ---- bin edges into packed CSR; weight pre-scaled by dinv[src] ----
__global__ void bin_kernel(const void* ei, const float* __restrict__ w, int E) {
    int e = blockIdx.x * blockDim.x + threadIdx.x;
    if (e >= E) return;
    int src, dst;
    decode_edge(ei, E, e, src, dst);
    float wn = w[e] * rsqrtf(1.0f + g_deg[src]);
    int pos = atomicAdd(&g_cur[dst], 1);
    g_csr[pos] = make_int2(src, __float_as_int(wn));
}

// ---------------------------------------------------------------------------
// Layer-2 GEMM: hs = g_act @ W2 (raw). g_act referenced inside device code.
// ---------------------------------------------------------------------------
__global__ __launch_bounds__(256) void gemm2_kernel(
    const float* __restrict__ W, int n)
{
    __shared__ float sW[HID * HID];
    for (int i = threadIdx.x; i < HID * HID; i += blockDim.x) sW[i] = W[i];
    __syncthreads();

    int row = blockIdx.x * blockDim.x + threadIdx.x;
    if (row >= n) return;

    float acc[HID];
    #pragma unroll
    for (int j = 0; j < HID; j++) acc[j] = 0.0f;

    const float4* xr = (const float4*)((const float*)g_act + (size_t)row * HID);
    #pragma unroll
    for (int k4 = 0; k4 < HID / 4; k4++) {
        float4 xv = __ldg(&xr[k4]);
        float xs[4] = {xv.x, xv.y, xv.z, xv.w};
        #pragma unroll
        for (int s = 0; s < 4; s++) {
            int k = k4 * 4 + s;
            float xk = xs[s];
            #pragma unroll
            for (int j4 = 0; j4 < HID / 4; j4++) {
                float4 wv = *(const float4*)&sW[k * HID + j4 * 4];
                acc[j4 * 4 + 0] += xk * wv.x;
                acc[j4 * 4 + 1] += xk * wv.y;
                acc[j4 * 4 + 2] += xk * wv.z;
                acc[j4 * 4 + 3] += xk * wv.w;
            }
        }
    }

    float4* ph = (float4*)&g_hs[(size_t)row * HID];
    #pragma unroll
    for (int j4 = 0; j4 < HID / 4; j4++) {
        ph[j4] = make_float4(acc[j4 * 4 + 0], acc[j4 * 4 + 1],
                             acc[j4 * 4 + 2], acc[j4 * 4 + 3]);
    }
}

// ---------------------------------------------------------------------------
// Aggregation: one warp per dst. Lane l owns features [2l, 2l+1].
// acc = dinv*h[dst] + sum_e w'_e * h[src_e];  out = dinv*acc + bias
// (w' pre-scaled by dinv[src] at bin time.)
//   MODE 0: g_act = relu(out);  MODE 1: outp = out
// ---------------------------------------------------------------------------
template <int MODE>
__global__ __launch_bounds__(256) void agg_kernel(
    const float* __restrict__ bias, float* __restrict__ outp, int n)
{
    int gtid = blockIdx.x * blockDim.x + threadIdx.x;
    int dst  = gtid >> 5;
    if (dst >= n) return;
    int lane = threadIdx.x & 31;

    int beg = g_offs[dst];
    int cnt = g_cnt[dst];
    float di = rsqrtf(1.0f + g_deg[dst]);

    float2 hself = *(const float2*)&g_hs[(size_t)dst * HID + lane * 2];
    float2 acc = make_float2(di * hself.x, di * hself.y);   // self-loop term

    for (int base = 0; base < cnt; base += 32) {
        int m = cnt - base; if (m > 32) m = 32;
        int   se = 0; float we = 0.0f;
        if (lane < m) {
            int2 ent = __ldg(&g_csr[beg + base + lane]);
            se = ent.x;
            we = __int_as_float(ent.y);
        }
        for (int t = 0; t < m; t++) {
            int   ss = __shfl_sync(0xffffffffu, se, t);
            float ww = __shfl_sync(0xffffffffu, we, t);
            float2 hv = __ldg((const float2*)&g_hs[(size_t)ss * HID + lane * 2]);
            acc.x += ww * hv.x;
            acc.y += ww * hv.y;
        }
    }

    float bx = bias[lane * 2], by = bias[lane * 2 + 1];
    float ox = di * acc.x + bx;
    float oy = di * acc.y + by;
    if (MODE == 0) {
        ox = fmaxf(ox, 0.0f);
        oy = fmaxf(oy, 0.0f);
        *(float2*)&g_act[(size_t)dst * HID + lane * 2] = make_float2(ox, oy);
    } else {
        *(float2*)&outp[(size_t)dst * HID + lane * 2] = make_float2(ox, oy);
    }
}

extern "C" void kernel_launch(void* const* d_in, const int* in_sizes, int n_in,
                              void* d_out, int out_size)
{
    const float* x  = (const float*)d_in[0];
    const void*  ei = d_in[1];               // int32 or int64, device-detected
    const float* ew = (const float*)d_in[2];
    const float* W1 = (const float*)d_in[3];
    const float* b1 = (const float*)d_in[4];
    const float* W2 = (const float*)d_in[5];
    const float* b2 = (const float*)d_in[6];
    float* out = (float*)d_out;

    int n = in_sizes[0] / HID;
    int E = in_sizes[2];

    const int T = 256;
    int gN   = (n + T - 1) / T;              // 391
    int gE   = (E + T - 1) / T;              // 4688
    int gN32 = (n * 32 + T - 1) / T;         // warp-per-node

    init_kernel      <<<gN, T>>>(ei, n);
    hist_gemm1_kernel<<<gE + gN, T>>>(ei, ew, x, W1, n, E, gE);
    scan1_kernel     <<<gN, 256>>>(n);
    scan23_kernel    <<<gN, 256>>>(n, gN);
    bin_kernel       <<<gE, T>>>(ei, ew, E);

    agg_kernel<0><<<gN32, T>>>(b1, nullptr, n);   // layer-1 aggregate + relu
    gemm2_kernel <<<gN, T>>>(W2, n);              // layer-2 transform
    agg_kernel<1><<<gN32, T>>>(b2, out, n);       // layer-2 aggregate -> out
}

// round 8
// speedup vs baseline: 1.2531x; 1.0345x over previous
#include <cuda_runtime.h>
#include <cstdint>

#define N_NODES 100000
#define E_MAX   1200000
#define HID 64

// ---- static device scratch (allocation-free) ----
__device__ float g_deg [N_NODES];            // sum of incoming edge weights (no self)
__device__ float g_hs  [N_NODES * HID];      // raw transformed features (XW)
__device__ float g_act [N_NODES * HID];      // layer-1 activations
__device__ int   g_cnt [N_NODES];            // in-degree count
__device__ int   g_offs[N_NODES];            // CSR exclusive offsets
__device__ int   g_cur [N_NODES];            // binning cursors
__device__ int   g_bsum[512];                // per-block count sums
__device__ int   g_scan_done;                // scan flag counter (zeroed in init)
__device__ int2  g_csr [E_MAX];              // CSR entry: {src, bits(w*dinv[src])}
__device__ int   g_is32;                     // edge_index dtype flag

// ---- packed f32x2 helpers (Blackwell FFMA2; PTX-only, ptxas won't fuse) ----
__device__ __forceinline__ unsigned long long pack2(float a, float b) {
    unsigned long long r;
    asm("mov.b64 %0, {%1, %2};" : "=l"(r)
        : "r"(__float_as_uint(a)), "r"(__float_as_uint(b)));
    return r;
}
__device__ __forceinline__ float2 unpack2(unsigned long long v) {
    unsigned lo, hi;
    asm("mov.b64 {%0, %1}, %2;" : "=r"(lo), "=r"(hi) : "l"(v));
    return make_float2(__uint_as_float(lo), __uint_as_float(hi));
}
__device__ __forceinline__ void fma2(unsigned long long& d,
                                     unsigned long long a, unsigned long long b) {
    asm("fma.rn.f32x2 %0, %1, %2, %3;" : "=l"(d) : "l"(a), "l"(b), "l"(d));
}

__device__ __forceinline__ void decode_edge(const void* ei, int E, int e,
                                            int& src, int& dst) {
    if (g_is32) {
        const int* p = (const int*)ei;
        src = p[e]; dst = p[E + e];
    } else {
        const long long* p = (const long long*)ei;
        src = (int)p[e]; dst = (int)p[E + e];
    }
}

// ---------------------------------------------------------------------------
// init: zero deg/cnt/scan flag, detect edge_index dtype.
// ---------------------------------------------------------------------------
__global__ void init_kernel(const void* ei, int n) {
    int i = blockIdx.x * blockDim.x + threadIdx.x;
    if (i < n) { g_deg[i] = 0.0f; g_cnt[i] = 0; }
    if (i == 0) {
        g_scan_done = 0;
        const long long* p = (const long long*)ei;
        int bad = 0;
        for (int k = 0; k < 64; k++) {
            long long v = p[k];
            if (v < 0 || v >= N_NODES) bad = 1;
        }
        g_is32 = bad;
    }
}

// ---------------------------------------------------------------------------
// Shared GEMM row body with packed FFMA2. Writes raw (unscaled) row to g_hs.
// ---------------------------------------------------------------------------
__device__ __forceinline__ void gemm_row_f32x2(
    const float* __restrict__ in_row, const float* sW, int row)
{
    unsigned long long acc2[HID / 2];
    #pragma unroll
    for (int j = 0; j < HID / 2; j++) acc2[j] = 0ULL;   // bits(+0.0f, +0.0f)

    const float4* xr = (const float4*)in_row;
    #pragma unroll
    for (int k4 = 0; k4 < HID / 4; k4++) {
        float4 xv = __ldg(&xr[k4]);
        float xs[4] = {xv.x, xv.y, xv.z, xv.w};
        #pragma unroll
        for (int s = 0; s < 4; s++) {
            int k = k4 * 4 + s;
            unsigned long long xk2 = pack2(xs[s], xs[s]);
            const ulonglong2* wp = (const ulonglong2*)&sW[k * HID];
            #pragma unroll
            for (int j2 = 0; j2 < HID / 4; j2++) {
                ulonglong2 wv = wp[j2];
                fma2(acc2[2 * j2 + 0], xk2, wv.x);
                fma2(acc2[2 * j2 + 1], xk2, wv.y);
            }
        }
    }

    float4* ph = (float4*)&g_hs[(size_t)row * HID];
    #pragma unroll
    for (int j4 = 0; j4 < HID / 4; j4++) {
        float2 p0 = unpack2(acc2[2 * j4 + 0]);
        float2 p1 = unpack2(acc2[2 * j4 + 1]);
        ph[j4] = make_float4(p0.x, p0.y, p1.x, p1.y);
    }
}

// ---------------------------------------------------------------------------
// Fused: blocks [0, gE) run the edge histogram (cnt++/deg+=w atomics);
// blocks [gE, gE+gN) run the layer-1 GEMM rows (hs = x @ W1, unscaled).
// ---------------------------------------------------------------------------
__global__ __launch_bounds__(256) void hist_gemm1_kernel(
    const void* ei, const float* __restrict__ w,
    const float* __restrict__ x, const float* __restrict__ W,
    int n, int E, int gE)
{
    if ((int)blockIdx.x < gE) {
        int e = blockIdx.x * blockDim.x + threadIdx.x;
        if (e >= E) return;
        int src, dst;
        decode_edge(ei, E, e, src, dst);
        atomicAdd(&g_cnt[dst], 1);
        atomicAdd(&g_deg[dst], w[e]);
        return;
    }

    __shared__ __align__(16) float sW[HID * HID];
    for (int i = threadIdx.x; i < HID * HID; i += blockDim.x) sW[i] = W[i];
    __syncthreads();

    int row = (blockIdx.x - gE) * blockDim.x + threadIdx.x;
    if (row >= n) return;
    gemm_row_f32x2(x + (size_t)row * HID, sW, row);
}

// ---------------------------------------------------------------------------
// Fused single-kernel scan: per-block Hillis-Steele scan of g_cnt, publish
// block sums, grid-wide flag spin (391 blocks << 1184 residency capacity:
// all wave-1 resident -> no deadlock), then add cross-block prefix.
// ---------------------------------------------------------------------------
__global__ __launch_bounds__(256) void scan_fused_kernel(int n, int nblocks) {
    __shared__ int s[256];
    int t = threadIdx.x;
    int bid = blockIdx.x;
    int i = bid * 256 + t;
    int v = (i < n) ? g_cnt[i] : 0;
    s[t] = v; __syncthreads();
    #pragma unroll
    for (int d = 1; d < 256; d <<= 1) {
        int x = (t >= d) ? s[t - d] : 0;
        __syncthreads();
        s[t] += x; __syncthreads();
    }
    int excl = s[t] - v;                        // exclusive within block

    if (t == 255) {
        g_bsum[bid] = s[255];                   // block total
        __threadfence();
        atomicAdd(&g_scan_done, 1);
    }
    if (t == 0) {
        while (atomicAdd(&g_scan_done, 0) < nblocks) {}
    }
    __syncthreads();

    int p = 0;
    for (int b = t; b < bid; b += 256) p += g_bsum[b];
    s[t] = p; __syncthreads();
    #pragma unroll
    for (int d = 128; d > 0; d >>= 1) {
        if (t < d) s[t] += s[t + d];
        __syncthreads();
    }
    int prefix = s[0];
    if (i < n) {
        int o = excl + prefix;
        g_offs[i] = o;
        g_cur[i]  = o;
    }
}

// ---- bin edges into packed CSR; weight pre-scaled by dinv[src] ----
__global__ void bin_kernel(const void* ei, const float* __restrict__ w, int E) {
    int e = blockIdx.x * blockDim.x + threadIdx.x;
    if (e >= E) return;
    int src, dst;
    decode_edge(ei, E, e, src, dst);
    float wn = w[e] * rsqrtf(1.0f + g_deg[src]);
    int pos = atomicAdd(&g_cur[dst], 1);
    g_csr[pos] = make_int2(src, __float_as_int(wn));
}

// ---------------------------------------------------------------------------
// Layer-2 GEMM: hs = g_act @ W2 (raw). g_act referenced inside device code.
// ---------------------------------------------------------------------------
__global__ __launch_bounds__(256) void gemm2_kernel(
    const float* __restrict__ W, int n)
{
    __shared__ __align__(16) float sW[HID * HID];
    for (int i = threadIdx.x; i < HID * HID; i += blockDim.x) sW[i] = W[i];
    __syncthreads();

    int row = blockIdx.x * blockDim.x + threadIdx.x;
    if (row >= n) return;
    gemm_row_f32x2((const float*)g_act + (size_t)row * HID, sW, row);
}

// ---------------------------------------------------------------------------
// Aggregation: one warp per dst. Lane l owns features [2l, 2l+1] as one
// packed f32x2 accumulator. acc = dinv*h[dst] + sum_e w'_e * h[src_e];
// out = dinv*acc + bias.  MODE 0: g_act = relu(out);  MODE 1: outp = out
// ---------------------------------------------------------------------------
template <int MODE>
__global__ __launch_bounds__(256) void agg_kernel(
    const float* __restrict__ bias, float* __restrict__ outp, int n)
{
    int gtid = blockIdx.x * blockDim.x + threadIdx.x;
    int dst  = gtid >> 5;
    if (dst >= n) return;
    int lane = threadIdx.x & 31;

    int beg = g_offs[dst];
    int cnt = g_cnt[dst];
    float di = rsqrtf(1.0f + g_deg[dst]);

    float2 hself = *(const float2*)&g_hs[(size_t)dst * HID + lane * 2];
    unsigned long long acc2 = pack2(di * hself.x, di * hself.y);  // self-loop

    for (int base = 0; base < cnt; base += 32) {
        int m = cnt - base; if (m > 32) m = 32;
        int   se = 0; float we = 0.0f;
        if (lane < m) {
            int2 ent = __ldg(&g_csr[beg + base + lane]);
            se = ent.x;
            we = __int_as_float(ent.y);
        }
        for (int t = 0; t < m; t++) {
            int   ss = __shfl_sync(0xffffffffu, se, t);
            float ww = __shfl_sync(0xffffffffu, we, t);
            unsigned long long hv2 =
                __ldg((const unsigned long long*)&g_hs[(size_t)ss * HID + lane * 2]);
            fma2(acc2, pack2(ww, ww), hv2);
        }
    }

    float2 a = unpack2(acc2);
    float bx = bias[lane * 2], by = bias[lane * 2 + 1];
    float ox = di * a.x + bx;
    float oy = di * a.y + by;
    if (MODE == 0) {
        ox = fmaxf(ox, 0.0f);
        oy = fmaxf(oy, 0.0f);
        *(float2*)&g_act[(size_t)dst * HID + lane * 2] = make_float2(ox, oy);
    } else {
        *(float2*)&outp[(size_t)dst * HID + lane * 2] = make_float2(ox, oy);
    }
}

extern "C" void kernel_launch(void* const* d_in, const int* in_sizes, int n_in,
                              void* d_out, int out_size)
{
    const float* x  = (const float*)d_in[0];
    const void*  ei = d_in[1];               // int32 or int64, device-detected
    const float* ew = (const float*)d_in[2];
    const float* W1 = (const float*)d_in[3];
    const float* b1 = (const float*)d_in[4];
    const float* W2 = (const float*)d_in[5];
    const float* b2 = (const float*)d_in[6];
    float* out = (float*)d_out;

    int n = in_sizes[0] / HID;
    int E = in_sizes[2];

    const int T = 256;
    int gN   = (n + T - 1) / T;              // 391
    int gE   = (E + T - 1) / T;              // 4688
    int gN32 = (n * 32 + T - 1) / T;         // warp-per-node

    init_kernel      <<<gN, T>>>(ei, n);                  // launch 0
    hist_gemm1_kernel<<<gE + gN, T>>>(ei, ew, x, W1, n, E, gE);  // 1
    scan_fused_kernel<<<gN, 256>>>(n, gN);                // 2
    bin_kernel       <<<gE, T>>>(ei, ew, E);              // 3 (profiled slot)

    agg_kernel<0><<<gN32, T>>>(b1, nullptr, n);           // 4: layer-1 agg+relu
    gemm2_kernel <<<gN, T>>>(W2, n);                      // 5: layer-2 transform
    agg_kernel<1><<<gN32, T>>>(b2, out, n);               // 6: layer-2 agg -> out
}

// round 9
// speedup vs baseline: 1.2892x; 1.0288x over previous
#include <cuda_runtime.h>
#include <cstdint>

#define N_NODES 100000
#define E_MAX   1200000
#define HID 64

// ---- static device scratch (allocation-free) ----
__device__ float g_deg [N_NODES];            // sum of incoming edge weights (no self)
__device__ float g_hs  [N_NODES * HID];      // raw transformed features (XW)
__device__ float g_act [N_NODES * HID];      // layer-1 activations
__device__ int   g_cnt [N_NODES];            // in-degree count
__device__ int   g_offs[N_NODES];            // CSR exclusive offsets
__device__ int   g_cur [N_NODES];            // binning cursors
__device__ int   g_bsum[512];                // per-block count sums
__device__ int   g_done1;                    // scan phase-1 flag (zeroed in init)
__device__ int   g_done2;                    // scan phase-2 flag (zeroed in init)
__device__ int2  g_csr [E_MAX];              // CSR entry: {src, bits(w*dinv[src])}
__device__ int   g_is32;                     // edge_index dtype flag

// ---- packed f32x2 helpers (Blackwell FFMA2; PTX-only, ptxas won't fuse) ----
__device__ __forceinline__ unsigned long long pack2(float a, float b) {
    unsigned long long r;
    asm("mov.b64 %0, {%1, %2};" : "=l"(r)
        : "r"(__float_as_uint(a)), "r"(__float_as_uint(b)));
    return r;
}
__device__ __forceinline__ float2 unpack2(unsigned long long v) {
    unsigned lo, hi;
    asm("mov.b64 {%0, %1}, %2;" : "=r"(lo), "=r"(hi) : "l"(v));
    return make_float2(__uint_as_float(lo), __uint_as_float(hi));
}
__device__ __forceinline__ void fma2(unsigned long long& d,
                                     unsigned long long a, unsigned long long b) {
    asm("fma.rn.f32x2 %0, %1, %2, %3;" : "=l"(d) : "l"(a), "l"(b), "l"(d));
}

__device__ __forceinline__ void decode_edge(const void* ei, int E, int e,
                                            int& src, int& dst) {
    if (g_is32) {
        const int* p = (const int*)ei;
        src = p[e]; dst = p[E + e];
    } else {
        const long long* p = (const long long*)ei;
        src = (int)p[e]; dst = (int)p[E + e];
    }
}

// ---------------------------------------------------------------------------
// init: zero deg/cnt/flags, detect edge_index dtype.
// ---------------------------------------------------------------------------
__global__ void init_kernel(const void* ei, int n) {
    int i = blockIdx.x * blockDim.x + threadIdx.x;
    if (i < n) { g_deg[i] = 0.0f; g_cnt[i] = 0; }
    if (i == 0) {
        g_done1 = 0;
        g_done2 = 0;
        const long long* p = (const long long*)ei;
        int bad = 0;
        for (int k = 0; k < 64; k++) {
            long long v = p[k];
            if (v < 0 || v >= N_NODES) bad = 1;
        }
        g_is32 = bad;
    }
}

// ---------------------------------------------------------------------------
// Shared GEMM row body with packed FFMA2. Writes raw (unscaled) row to g_hs.
// ---------------------------------------------------------------------------
__device__ __forceinline__ void gemm_row_f32x2(
    const float* __restrict__ in_row, const float* sW, int row)
{
    unsigned long long acc2[HID / 2];
    #pragma unroll
    for (int j = 0; j < HID / 2; j++) acc2[j] = 0ULL;   // bits(+0.0f, +0.0f)

    const float4* xr = (const float4*)in_row;
    #pragma unroll
    for (int k4 = 0; k4 < HID / 4; k4++) {
        float4 xv = __ldg(&xr[k4]);
        float xs[4] = {xv.x, xv.y, xv.z, xv.w};
        #pragma unroll
        for (int s = 0; s < 4; s++) {
            int k = k4 * 4 + s;
            unsigned long long xk2 = pack2(xs[s], xs[s]);
            const ulonglong2* wp = (const ulonglong2*)&sW[k * HID];
            #pragma unroll
            for (int j2 = 0; j2 < HID / 4; j2++) {
                ulonglong2 wv = wp[j2];
                fma2(acc2[2 * j2 + 0], xk2, wv.x);
                fma2(acc2[2 * j2 + 1], xk2, wv.y);
            }
        }
    }

    float4* ph = (float4*)&g_hs[(size_t)row * HID];
    #pragma unroll
    for (int j4 = 0; j4 < HID / 4; j4++) {
        float2 p0 = unpack2(acc2[2 * j4 + 0]);
        float2 p1 = unpack2(acc2[2 * j4 + 1]);
        ph[j4] = make_float4(p0.x, p0.y, p1.x, p1.y);
    }
}

// ---------------------------------------------------------------------------
// Fused: blocks [0, gE) run the edge histogram (cnt++/deg+=w atomics);
// blocks [gE, gE+gN) run the layer-1 GEMM rows (hs = x @ W1, unscaled).
// ---------------------------------------------------------------------------
__global__ __launch_bounds__(256) void hist_gemm1_kernel(
    const void* ei, const float* __restrict__ w,
    const float* __restrict__ x, const float* __restrict__ W,
    int n, int E, int gE)
{
    if ((int)blockIdx.x < gE) {
        int e = blockIdx.x * blockDim.x + threadIdx.x;
        if (e >= E) return;
        int src, dst;
        decode_edge(ei, E, e, src, dst);
        atomicAdd(&g_cnt[dst], 1);
        atomicAdd(&g_deg[dst], w[e]);
        return;
    }

    __shared__ __align__(16) float sW[HID * HID];
    for (int i = threadIdx.x; i < HID * HID; i += blockDim.x) sW[i] = W[i];
    __syncthreads();

    int row = (blockIdx.x - gE) * blockDim.x + threadIdx.x;
    if (row >= n) return;
    gemm_row_f32x2(x + (size_t)row * HID, sW, row);
}

// ---------------------------------------------------------------------------
// Fused scan + bin, one kernel (grid = gE blocks):
//  phase A (blocks < nsb): block-local scan of g_cnt, publish block sums,
//  grid flag 1; redundant cross-block prefix; write g_offs/g_cur; flag 2.
//  phase B (all blocks): wait flag 2, then bin this block's edge slice.
//  Deadlock-free: the nsb=391 scan blocks all fit in wave 1 (>=4 CTAs/SM).
// ---------------------------------------------------------------------------
__global__ __launch_bounds__(256) void scanbin_kernel(
    const void* ei, const float* __restrict__ w, int n, int E, int nsb)
{
    __shared__ int s[256];
    int t = threadIdx.x;
    int bid = blockIdx.x;

    if (bid < nsb) {
        int i = bid * 256 + t;
        int v = (i < n) ? g_cnt[i] : 0;
        s[t] = v; __syncthreads();
        #pragma unroll
        for (int d = 1; d < 256; d <<= 1) {
            int x = (t >= d) ? s[t - d] : 0;
            __syncthreads();
            s[t] += x; __syncthreads();
        }
        int excl = s[t] - v;                    // exclusive within block

        if (t == 255) {
            g_bsum[bid] = s[255];
            __threadfence();
            atomicAdd(&g_done1, 1);
        }
        if (t == 0) {
            while (atomicAdd(&g_done1, 0) < nsb) __nanosleep(64);
        }
        __syncthreads();

        int p = 0;
        for (int b = t; b < bid; b += 256) p += g_bsum[b];
        s[t] = p; __syncthreads();
        #pragma unroll
        for (int d = 128; d > 0; d >>= 1) {
            if (t < d) s[t] += s[t + d];
            __syncthreads();
        }
        int prefix = s[0];
        if (i < n) {
            int o = excl + prefix;
            g_offs[i] = o;
            g_cur[i]  = o;
        }
        __syncthreads();
        if (t == 0) {
            __threadfence();
            atomicAdd(&g_done2, 1);
        }
    }

    // ---- phase B: everyone waits for all cursors, then bins ----
    if (t == 0) {
        while (atomicAdd(&g_done2, 0) < nsb) __nanosleep(64);
    }
    __syncthreads();

    int e = bid * 256 + t;
    if (e >= E) return;
    int src, dst;
    decode_edge(ei, E, e, src, dst);
    float wn = w[e] * rsqrtf(1.0f + g_deg[src]);
    int pos = atomicAdd(&g_cur[dst], 1);
    g_csr[pos] = make_int2(src, __float_as_int(wn));
}

// ---------------------------------------------------------------------------
// Layer-2 GEMM: hs = g_act @ W2 (raw). g_act referenced inside device code.
// ---------------------------------------------------------------------------
__global__ __launch_bounds__(256) void gemm2_kernel(
    const float* __restrict__ W, int n)
{
    __shared__ __align__(16) float sW[HID * HID];
    for (int i = threadIdx.x; i < HID * HID; i += blockDim.x) sW[i] = W[i];
    __syncthreads();

    int row = blockIdx.x * blockDim.x + threadIdx.x;
    if (row >= n) return;
    gemm_row_f32x2((const float*)g_act + (size_t)row * HID, sW, row);
}

// ---------------------------------------------------------------------------
// Aggregation: one warp per dst. Lane l owns features [2l, 2l+1] packed.
// 2-edge ILP: two independent LDG.64 in flight, dual accumulators.
//   MODE 0: g_act = relu(dinv*acc + bias);  MODE 1: outp = dinv*acc + bias
// ---------------------------------------------------------------------------
template <int MODE>
__global__ __launch_bounds__(256) void agg_kernel(
    const float* __restrict__ bias, float* __restrict__ outp, int n)
{
    int gtid = blockIdx.x * blockDim.x + threadIdx.x;
    int dst  = gtid >> 5;
    if (dst >= n) return;
    int lane = threadIdx.x & 31;

    int beg = g_offs[dst];
    int cnt = g_cnt[dst];
    float di = rsqrtf(1.0f + g_deg[dst]);

    float2 hself = *(const float2*)&g_hs[(size_t)dst * HID + lane * 2];
    unsigned long long accA = pack2(di * hself.x, di * hself.y);  // self-loop
    unsigned long long accB = 0ULL;

    for (int base = 0; base < cnt; base += 32) {
        int m = cnt - base; if (m > 32) m = 32;
        int   se = 0; float we = 0.0f;
        if (lane < m) {
            int2 ent = __ldg(&g_csr[beg + base + lane]);
            se = ent.x;
            we = __int_as_float(ent.y);
        }
        int t = 0;
        for (; t + 2 <= m; t += 2) {
            int   s0 = __shfl_sync(0xffffffffu, se, t);
            float w0 = __shfl_sync(0xffffffffu, we, t);
            int   s1 = __shfl_sync(0xffffffffu, se, t + 1);
            float w1 = __shfl_sync(0xffffffffu, we, t + 1);
            unsigned long long h0 =
                __ldg((const unsigned long long*)&g_hs[(size_t)s0 * HID + lane * 2]);
            unsigned long long h1 =
                __ldg((const unsigned long long*)&g_hs[(size_t)s1 * HID + lane * 2]);
            fma2(accA, pack2(w0, w0), h0);
            fma2(accB, pack2(w1, w1), h1);
        }
        if (t < m) {
            int   s0 = __shfl_sync(0xffffffffu, se, t);
            float w0 = __shfl_sync(0xffffffffu, we, t);
            unsigned long long h0 =
                __ldg((const unsigned long long*)&g_hs[(size_t)s0 * HID + lane * 2]);
            fma2(accA, pack2(w0, w0), h0);
        }
    }

    float2 a = unpack2(accA);
    float2 b = unpack2(accB);
    float ax = a.x + b.x, ay = a.y + b.y;
    float bx = bias[lane * 2], by = bias[lane * 2 + 1];
    float ox = di * ax + bx;
    float oy = di * ay + by;
    if (MODE == 0) {
        ox = fmaxf(ox, 0.0f);
        oy = fmaxf(oy, 0.0f);
        *(float2*)&g_act[(size_t)dst * HID + lane * 2] = make_float2(ox, oy);
    } else {
        *(float2*)&outp[(size_t)dst * HID + lane * 2] = make_float2(ox, oy);
    }
}

extern "C" void kernel_launch(void* const* d_in, const int* in_sizes, int n_in,
                              void* d_out, int out_size)
{
    const float* x  = (const float*)d_in[0];
    const void*  ei = d_in[1];               // int32 or int64, device-detected
    const float* ew = (const float*)d_in[2];
    const float* W1 = (const float*)d_in[3];
    const float* b1 = (const float*)d_in[4];
    const float* W2 = (const float*)d_in[5];
    const float* b2 = (const float*)d_in[6];
    float* out = (float*)d_out;

    int n = in_sizes[0] / HID;
    int E = in_sizes[2];

    const int T = 256;
    int gN   = (n + T - 1) / T;              // 391
    int gE   = (E + T - 1) / T;              // 4688
    int gN32 = (n * 32 + T - 1) / T;         // warp-per-node

    init_kernel      <<<gN, T>>>(ei, n);                         // 0
    hist_gemm1_kernel<<<gE + gN, T>>>(ei, ew, x, W1, n, E, gE);  // 1
    scanbin_kernel   <<<gE, T>>>(ei, ew, n, E, gN);              // 2

    agg_kernel<0><<<gN32, T>>>(b1, nullptr, n);                  // 3 (profiled)
    gemm2_kernel <<<gN, T>>>(W2, n);                             // 4
    agg_kernel<1><<<gN32, T>>>(b2, out, n);                      // 5
}